// round 3
// baseline (speedup 1.0000x reference)
#include <cuda_runtime.h>
#include <cstdint>

#define BB 64
#define TT 1024
#define HH 256
#define NG 4

typedef unsigned long long ull;

// ---------------- device scratch ----------------
__device__ float g_Aih[256 * 64];          // [d][o], o = g*16+s
__device__ float g_Ahh[256 * 64];          // [d][o]
__device__ float g_Bc [4 * 32 * 256];      // [g][s2][j]; s2<16: ih, s2>=16: hh
__device__ float g_bias[4 * 256];          // [g][j]
__device__ float g_Z  [BB * TT * 64];      // [n][o]

// ---------------- packed f32x2 helpers ----------------
__device__ __forceinline__ ull ffma2(ull a, ull b, ull c) {
    ull d;
    asm("fma.rn.f32x2 %0, %1, %2, %3;" : "=l"(d) : "l"(a), "l"(b), "l"(c));
    return d;
}
__device__ __forceinline__ ull pack2(float lo, float hi) {
    ull r; asm("mov.b64 %0, {%1,%2};" : "=l"(r) : "f"(lo), "f"(hi)); return r;
}
__device__ __forceinline__ float hsum2(ull v) {
    float lo, hi; asm("mov.b64 {%0,%1}, %2;" : "=f"(lo), "=f"(hi) : "l"(v));
    return lo + hi;
}

__device__ __forceinline__ float sigmoid_f(float x) {
    x = fminf(fmaxf(x, -30.f), 30.f);
    return __fdividef(1.f, 1.f + __expf(-x));
}
__device__ __forceinline__ float tanh_f(float x) {
    float xc = fminf(fmaxf(x, -15.f), 15.f);
    float e = __expf(-2.f * xc);
    return __fdividef(1.f - e, 1.f + e);
}

// ---------------- kernel A: compose rank-16 factors ----------------
__global__ void compose_kernel(const float* __restrict__ ih0, const float* __restrict__ ih1,
                               const float* __restrict__ ih2, const float* __restrict__ ih3,
                               const float* __restrict__ ihb,
                               const float* __restrict__ hh0, const float* __restrict__ hh1,
                               const float* __restrict__ hh2, const float* __restrict__ hh3,
                               const float* __restrict__ hhb) {
    int tid = blockIdx.x * blockDim.x + threadIdx.x;
    int stride = gridDim.x * blockDim.x;
    for (int idx = tid; idx < 4 * 256 * 16; idx += stride) {
        int s = idx & 15;
        int d = (idx >> 4) & 255;
        int g = idx >> 12;
        int m = d >> 4, n = d & 15;
        float a_ih = 0.f, a_hh = 0.f;
        #pragma unroll
        for (int r = 0; r < 16; r++) {
            a_ih += ih0[(g * 16 + m) * 16 + r] * ih1[((g * 16 + r) * 16 + n) * 16 + s];
            a_hh += hh0[(g * 16 + m) * 16 + r] * hh1[((g * 16 + r) * 16 + n) * 16 + s];
        }
        g_Aih[d * 64 + g * 16 + s] = a_ih;
        g_Ahh[d * 64 + g * 16 + s] = a_hh;
    }
    for (int idx = tid; idx < 4 * 16 * 256; idx += stride) {
        int j = idx & 255;
        int s = (idx >> 8) & 15;
        int g = idx >> 12;
        int o = j >> 4, p = j & 15;
        float b_ih = 0.f, b_hh = 0.f;
        #pragma unroll
        for (int t = 0; t < 16; t++) {
            b_ih += ih2[((g * 16 + s) * 16 + o) * 16 + t] * ih3[(g * 16 + t) * 16 + p];
            b_hh += hh2[((g * 16 + s) * 16 + o) * 16 + t] * hh3[(g * 16 + t) * 16 + p];
        }
        g_Bc[(g * 32 + s) * 256 + j]      = b_ih;
        g_Bc[(g * 32 + 16 + s) * 256 + j] = b_hh;
    }
    for (int idx = tid; idx < 1024; idx += stride)
        g_bias[idx] = ihb[idx] + hhb[idx];
}

// ---------------- kernel B: Z = X @ A_ih ----------------
__global__ __launch_bounds__(256) void z_kernel(const float* __restrict__ x) {
    __shared__ __align__(16) float xs[256];
    int tid = threadIdx.x;
    int o  = tid >> 2;     // 0..63
    int kq = tid & 3;

    ull wa2[32];
    #pragma unroll
    for (int i = 0; i < 32; i++)
        wa2[i] = pack2(g_Aih[(kq * 64 + 2 * i) * 64 + o],
                       g_Aih[(kq * 64 + 2 * i + 1) * 64 + o]);

    for (int n = blockIdx.x; n < BB * TT; n += gridDim.x) {
        __syncthreads();
        xs[tid] = x[n * 256 + tid];
        __syncthreads();
        const ulonglong2* hp = (const ulonglong2*)(xs + kq * 64);
        ull acc_a = 0ULL, acc_b = 0ULL;
        #pragma unroll
        for (int i2 = 0; i2 < 16; i2++) {
            ulonglong2 v = hp[i2];
            acc_a = ffma2(wa2[2 * i2],     v.x, acc_a);
            acc_b = ffma2(wa2[2 * i2 + 1], v.y, acc_b);
        }
        float acc = hsum2(acc_a) + hsum2(acc_b);
        acc += __shfl_xor_sync(0xffffffffu, acc, 1);
        acc += __shfl_xor_sync(0xffffffffu, acc, 2);
        if (kq == 0) g_Z[n * 64 + o] = acc;
    }
}

// ---------------- kernel C: recurrent scan, 1024 threads per batch ----------------
__global__ __launch_bounds__(1024, 1) void scan_kernel(float* __restrict__ out, int write_hc) {
    __shared__ __align__(16) float hs[256];      // h_{t-1}
    __shared__ __align__(16) float zc[4][32];    // [g][s2]: s2<16 ih, s2>=16 hh
    __shared__ __align__(16) float gs[4][256];   // gate pre-activations

    int tid = threadIdx.x;
    int b   = blockIdx.x;

    // ---- stage-1 role: 16 threads per output o ----
    int o  = tid >> 4;     // 0..63
    int ks = tid & 15;     // k-sixteenth: covers h[ks*16 .. ks*16+15]
    ull wa2[8];
    #pragma unroll
    for (int i = 0; i < 8; i++)
        wa2[i] = pack2(g_Ahh[(ks * 16 + 2 * i) * 64 + o],
                       g_Ahh[(ks * 16 + 2 * i + 1) * 64 + o]);

    // ---- stage-2 role: one thread per (gate g, column j) ----
    int g2 = tid >> 8;     // 0..3
    int j  = tid & 255;
    ull wb2[16];
    #pragma unroll
    for (int i = 0; i < 16; i++)
        wb2[i] = pack2(g_Bc[(g2 * 32 + 2 * i) * 256 + j],
                       g_Bc[(g2 * 32 + 2 * i + 1) * 256 + j]);
    float bias_r = g_bias[g2 * 256 + j];

    // ---- cell role: threads 0..255 own column tid ----
    float c = 0.f;
    if (tid < 256) hs[tid] = 0.f;
    float zreg = (tid < 64) ? g_Z[((size_t)b * TT) * 64 + tid] : 0.f;
    __syncthreads();

    const float* zbase = g_Z + (size_t)b * TT * 64;
    float* outb = out + (size_t)b * TT * HH;

    for (int t = 0; t < TT; t++) {
        // deposit prefetched z_ih, start next prefetch
        if (tid < 64) {
            zc[tid >> 4][tid & 15] = zreg;
            if (t < TT - 1) zreg = zbase[(size_t)(t + 1) * 64 + tid];
        }

        // stage 1: zh[o] = sum_k Ahh[k][o] h[k], 16-way split + shfl reduce
        {
            const ulonglong2* hp = (const ulonglong2*)(hs + ks * 16);
            ull a0 = 0ULL, a1 = 0ULL;
            #pragma unroll
            for (int i = 0; i < 4; i++) {
                ulonglong2 v = hp[i];
                a0 = ffma2(wa2[2 * i],     v.x, a0);
                a1 = ffma2(wa2[2 * i + 1], v.y, a1);
            }
            float acc = hsum2(a0) + hsum2(a1);
            acc += __shfl_xor_sync(0xffffffffu, acc, 1);
            acc += __shfl_xor_sync(0xffffffffu, acc, 2);
            acc += __shfl_xor_sync(0xffffffffu, acc, 4);
            acc += __shfl_xor_sync(0xffffffffu, acc, 8);
            if (ks == 0) zc[o >> 4][16 + (o & 15)] = acc;
        }
        __syncthreads();   // sync1: zc complete

        // stage 2: gate pre-activation for (g2, j), 32-term dot (zc broadcast)
        {
            const ulonglong2* zp = (const ulonglong2*)(zc[g2]);
            ull b0 = 0ULL, b1 = 0ULL;
            #pragma unroll
            for (int i = 0; i < 8; i++) {
                ulonglong2 v = zp[i];
                b0 = ffma2(wb2[2 * i],     v.x, b0);
                b1 = ffma2(wb2[2 * i + 1], v.y, b1);
            }
            gs[g2][j] = hsum2(b0) + hsum2(b1) + bias_r;
        }
        __syncthreads();   // sync2: gates complete

        // cell update on threads 0..255
        if (tid < 256) {
            float i_ = sigmoid_f(gs[0][tid]);
            float f_ = sigmoid_f(gs[1][tid]);
            float g_ = tanh_f(gs[2][tid]);
            float o_ = sigmoid_f(gs[3][tid]);
            c = f_ * c + i_ * g_;
            float h = o_ * tanh_f(c);
            hs[tid] = h;
            outb[(size_t)t * HH + tid] = h;
        }
        __syncthreads();   // sync3: hs ready for next stage 1
    }

    if (write_hc && tid < 256) {
        out[(size_t)BB * TT * HH + b * HH + tid]           = hs[tid];
        out[(size_t)BB * TT * HH + BB * HH + b * HH + tid] = c;
    }
}

// ---------------- launch ----------------
extern "C" void kernel_launch(void* const* d_in, const int* in_sizes, int n_in,
                              void* d_out, int out_size) {
    const float* x   = (const float*)d_in[0];
    const float* ih0 = (const float*)d_in[1];
    const float* ih1 = (const float*)d_in[2];
    const float* ih2 = (const float*)d_in[3];
    const float* ih3 = (const float*)d_in[4];
    const float* ihb = (const float*)d_in[5];
    const float* hh0 = (const float*)d_in[6];
    const float* hh1 = (const float*)d_in[7];
    const float* hh2 = (const float*)d_in[8];
    const float* hh3 = (const float*)d_in[9];
    const float* hhb = (const float*)d_in[10];

    compose_kernel<<<64, 256>>>(ih0, ih1, ih2, ih3, ihb, hh0, hh1, hh2, hh3, hhb);
    z_kernel<<<592, 256>>>(x);

    long long need = (long long)BB * TT * HH + 2LL * BB * HH;
    int whc = ((long long)out_size >= need) ? 1 : 0;
    scan_kernel<<<BB, 1024>>>((float*)d_out, whc);
}